// round 4
// baseline (speedup 1.0000x reference)
#include <cuda_runtime.h>
#include <cstdint>

#define SEG 256            // elements per segment (one warp reduces one segment)
#define MAXSEG 256         // smem capacity: supports V up to 65536

// ---------------------------------------------------------------------------
// Fused inverse-CDF sampler: one CTA (256 threads, 8 warps) per row.
//  Phase 1: warp w reduces segments {w, w+8, ...} -> smem segment sums
//  Phase 2: 256-thread block inclusive scan of segment sums
//  Phase 3: first segment with inclusive sum >= r (atomicMin), warp 0
//           re-reads that segment and counts ordered prefixes < r
//           (matches reference's  sample = #{v : rng > csum[v]})
// Output written as FLOAT (samples <= 32000 are exact in fp32).
// ---------------------------------------------------------------------------
__global__ void __launch_bounds__(256) sampler_kernel(
    const float* __restrict__ p, const float* __restrict__ rng,
    float* __restrict__ out, int V, int nseg)
{
    const int row  = blockIdx.x;
    const int t    = threadIdx.x;
    const int lane = t & 31;
    const int warp = t >> 5;                 // 0..7

    __shared__ float s_seg[MAXSEG];          // segment sums, then inclusive sums
    __shared__ float s_wsum[8];
    __shared__ int   s_min;

    const float* __restrict__ prow = p + (size_t)row * V;

    // ---- Phase 1: coalesced segment sums ----
    for (int s = warp; s < nseg; s += 8) {
        const int base = s * SEG;
        float v = 0.0f;
        if (V - base >= SEG) {
            float4 a = *reinterpret_cast<const float4*>(prow + base + lane * 4);
            float4 b = *reinterpret_cast<const float4*>(prow + base + 128 + lane * 4);
            v = (a.x + a.y) + (a.z + a.w) + (b.x + b.y) + (b.z + b.w);
        } else {
            for (int i = base + lane; i < V; i += 32) v += prow[i];
        }
        #pragma unroll
        for (int d = 16; d > 0; d >>= 1)
            v += __shfl_xor_sync(0xFFFFFFFFu, v, d);
        if (lane == 0) s_seg[s] = v;
    }
    if (t == 0) s_min = nseg;
    __syncthreads();

    // ---- Phase 2: block inclusive scan over nseg entries ----
    float x = (t < nseg) ? s_seg[t] : 0.0f;
    float ix = x;
    #pragma unroll
    for (int d = 1; d < 32; d <<= 1) {
        float y = __shfl_up_sync(0xFFFFFFFFu, ix, d);
        if (lane >= d) ix += y;
    }
    if (lane == 31) s_wsum[warp] = ix;
    __syncthreads();

    float off = 0.0f;
    #pragma unroll
    for (int w = 0; w < 8; w++)
        if (w < warp) off += s_wsum[w];
    const float incl = ix + off;
    __syncthreads();                          // done reading s_seg raw values
    if (t < nseg) s_seg[t] = incl;            // overwrite with inclusive sums
    const float r = __ldg(&rng[row]);
    __syncthreads();

    // ---- Phase 3: locate crossing segment ----
    if (t < nseg && incl >= r) atomicMin(&s_min, t);
    __syncthreads();

    const int sstar = s_min;
    if (sstar >= nseg) {                      // rng above total mass
        if (t == 0) out[row] = (float)V;
        return;
    }

    if (warp == 0) {
        float carry = (sstar > 0) ? s_seg[sstar - 1] : 0.0f;
        const int base = sstar * SEG;
        int cnt = 0;
        #pragma unroll
        for (int h = 0; h < 2; h++) {
            const int idx = base + h * 128 + lane * 4;
            float4 a = make_float4(0.f, 0.f, 0.f, 0.f);
            if (idx + 3 < V) {
                a = *reinterpret_cast<const float4*>(prow + idx);
            } else {
                if (idx + 0 < V) a.x = prow[idx + 0];
                if (idx + 1 < V) a.y = prow[idx + 1];
                if (idx + 2 < V) a.z = prow[idx + 2];
            }
            const float s4 = a.x + a.y + a.z + a.w;
            float scan = s4;
            #pragma unroll
            for (int d = 1; d < 32; d <<= 1) {
                float y = __shfl_up_sync(0xFFFFFFFFu, scan, d);
                if (lane >= d) scan += y;
            }
            const float excl = scan - s4;
            const float c0 = carry + excl + a.x;
            const float c1 = c0 + a.y;
            const float c2 = c1 + a.z;
            const float c3 = c2 + a.w;
            cnt += (idx + 0 < V && c0 < r);
            cnt += (idx + 1 < V && c1 < r);
            cnt += (idx + 2 < V && c2 < r);
            cnt += (idx + 3 < V && c3 < r);
            carry += __shfl_sync(0xFFFFFFFFu, scan, 31);
        }
        #pragma unroll
        for (int d = 16; d > 0; d >>= 1)
            cnt += __shfl_xor_sync(0xFFFFFFFFu, cnt, d);
        if (lane == 0) out[row] = (float)(base + cnt);
    }
}

extern "C" void kernel_launch(void* const* d_in, const int* in_sizes, int n_in,
                              void* d_out, int out_size) {
    // Resolve inputs by element count (p is the huge one, rng has `rows`).
    int ip = 0;
    for (int i = 1; i < n_in; i++)
        if (in_sizes[i] > in_sizes[ip]) ip = i;
    const float* p = (const float*)d_in[ip];

    const int rows = out_size;                       // B*T = 8192
    int ir = (ip == 0) ? 1 : 0;
    for (int i = 0; i < n_in; i++)
        if (i != ip && in_sizes[i] == rows) { ir = i; break; }
    const float* rng = (const float*)d_in[ir];

    float* out = (float*)d_out;                      // output dtype: float32

    const long long pelems = (long long)in_sizes[ip];
    const int V    = (int)(pelems / rows);           // 32000
    const int nseg = (V + SEG - 1) / SEG;            // 125

    sampler_kernel<<<rows, 256>>>(p, rng, out, V, nseg);
}

// round 5
// speedup vs baseline: 1.5556x; 1.5556x over previous
#include <cuda_runtime.h>
#include <cstdint>

#define SEG    256          // elements per segment (one warp reduces one segment)
#define MAXSEG 256          // smem capacity: supports V up to 65536
#define RSEGS  16           // segments per round (16 KB) — early-exit granularity

// ---------------------------------------------------------------------------
// Early-exit inverse-CDF sampler. One CTA (256 thr / 8 warps) per row.
// Rounds of 16 segments: 8 warps × 2 segment sums (4 independent float4
// loads each), stop at the first round whose cumulative sum >= r.
// Elements past the crossing can never change  #{v : r > csum[v]}.
// Then: locate crossing segment in the round, warp 0 recounts inside it
// with an ordered prefix (strict <, matching the reference).
// Output dtype is float32 (samples <= 32000 exact in fp32).
// ---------------------------------------------------------------------------
__global__ void __launch_bounds__(256) sampler_kernel(
    const float* __restrict__ p, const float* __restrict__ rng,
    float* __restrict__ out, int V, int nseg)
{
    const int row  = blockIdx.x;
    const int t    = threadIdx.x;
    const int lane = t & 31;
    const int warp = t >> 5;                  // 0..7

    __shared__ float s_seg[MAXSEG];           // per-segment sums (filled as we go)
    __shared__ float s_cum;                   // cumsum at end of current round
    __shared__ int   s_star;                  // crossing segment (-1 = none)
    __shared__ float s_pexcl;                 // exclusive prefix before s_star

    const float r = __ldg(&rng[row]);
    const float* __restrict__ prow = p + (size_t)row * V;

    float cumul = 0.0f;                       // cumsum before current round
    int s0 = 0;                               // first segment of current round
    int nIn = 0;

    for (;;) {
        nIn = (nseg - s0 < RSEGS) ? (nseg - s0) : RSEGS;

        // --- warp computes up to 2 segment sums with independent loads ---
        const int  sA  = s0 + warp;
        const int  sB  = s0 + 8 + warp;
        const bool doA = (warp < nIn);
        const bool doB = (8 + warp < nIn);

        float vA = 0.0f, vB = 0.0f;
        if (doA) {
            const int base = sA * SEG;
            if (base + SEG <= V) {
                float4 a0 = *reinterpret_cast<const float4*>(prow + base + lane * 4);
                float4 a1 = *reinterpret_cast<const float4*>(prow + base + 128 + lane * 4);
                vA = (a0.x + a0.y) + (a0.z + a0.w) + (a1.x + a1.y) + (a1.z + a1.w);
            } else {
                for (int i = base + lane; i < V; i += 32) vA += prow[i];
            }
        }
        if (doB) {
            const int base = sB * SEG;
            if (base + SEG <= V) {
                float4 b0 = *reinterpret_cast<const float4*>(prow + base + lane * 4);
                float4 b1 = *reinterpret_cast<const float4*>(prow + base + 128 + lane * 4);
                vB = (b0.x + b0.y) + (b0.z + b0.w) + (b1.x + b1.y) + (b1.z + b1.w);
            } else {
                for (int i = base + lane; i < V; i += 32) vB += prow[i];
            }
        }
        #pragma unroll
        for (int d = 16; d > 0; d >>= 1) {    // two interleaved reduction chains
            vA += __shfl_xor_sync(0xFFFFFFFFu, vA, d);
            vB += __shfl_xor_sync(0xFFFFFFFFu, vB, d);
        }
        if (lane == 0) {
            if (doA) s_seg[sA] = vA;
            if (doB) s_seg[sB] = vB;
        }
        __syncthreads();

        // --- round total + early-exit decision ---
        if (t == 0) {
            float c = cumul;
            for (int i = 0; i < nIn; i++) c += s_seg[s0 + i];
            s_cum = c;
        }
        __syncthreads();
        const float nc = s_cum;
        if (nc >= r || s0 + nIn >= nseg) break;
        cumul = nc;
        s0 += nIn;
    }

    // --- locate crossing segment within the final round ---
    if (t == 0) {
        float c = cumul;
        int   st = -1;
        float pe = cumul;
        for (int i = 0; i < nIn; i++) {
            const float nv = c + s_seg[s0 + i];
            if (nv >= r) { st = s0 + i; pe = c; break; }
            c = nv;
        }
        s_star  = st;
        s_pexcl = pe;
    }
    __syncthreads();

    const int sstar = s_star;
    if (sstar < 0) {                          // rng above total mass
        if (t == 0) out[row] = (float)V;
        return;
    }

    // --- warp 0: ordered recount inside the crossing segment ---
    if (warp == 0) {
        float carry = s_pexcl;
        const int base = sstar * SEG;
        int cnt = 0;
        #pragma unroll
        for (int h = 0; h < 2; h++) {
            const int idx = base + h * 128 + lane * 4;
            float4 a = make_float4(0.f, 0.f, 0.f, 0.f);
            if (idx + 3 < V) {
                a = *reinterpret_cast<const float4*>(prow + idx);
            } else {
                if (idx + 0 < V) a.x = prow[idx + 0];
                if (idx + 1 < V) a.y = prow[idx + 1];
                if (idx + 2 < V) a.z = prow[idx + 2];
            }
            const float s4 = a.x + a.y + a.z + a.w;
            float scan = s4;
            #pragma unroll
            for (int d = 1; d < 32; d <<= 1) {
                float y = __shfl_up_sync(0xFFFFFFFFu, scan, d);
                if (lane >= d) scan += y;
            }
            const float excl = scan - s4;
            const float c0 = carry + excl + a.x;
            const float c1 = c0 + a.y;
            const float c2 = c1 + a.z;
            const float c3 = c2 + a.w;
            cnt += (idx + 0 < V && c0 < r);
            cnt += (idx + 1 < V && c1 < r);
            cnt += (idx + 2 < V && c2 < r);
            cnt += (idx + 3 < V && c3 < r);
            carry += __shfl_sync(0xFFFFFFFFu, scan, 31);
        }
        #pragma unroll
        for (int d = 16; d > 0; d >>= 1)
            cnt += __shfl_xor_sync(0xFFFFFFFFu, cnt, d);
        if (lane == 0) out[row] = (float)(base + cnt);
    }
}

extern "C" void kernel_launch(void* const* d_in, const int* in_sizes, int n_in,
                              void* d_out, int out_size) {
    // Resolve inputs by element count (p is the huge one, rng has `rows`).
    int ip = 0;
    for (int i = 1; i < n_in; i++)
        if (in_sizes[i] > in_sizes[ip]) ip = i;
    const float* p = (const float*)d_in[ip];

    const int rows = out_size;                       // B*T = 8192
    int ir = (ip == 0) ? 1 : 0;
    for (int i = 0; i < n_in; i++)
        if (i != ip && in_sizes[i] == rows) { ir = i; break; }
    const float* rng = (const float*)d_in[ir];

    float* out = (float*)d_out;                      // output dtype: float32

    const long long pelems = (long long)in_sizes[ip];
    const int V    = (int)(pelems / rows);           // 32000
    const int nseg = (V + SEG - 1) / SEG;            // 125

    sampler_kernel<<<rows, 256>>>(p, rng, out, V, nseg);
}

// round 6
// speedup vs baseline: 2.7550x; 1.7711x over previous
#include <cuda_runtime.h>
#include <cstdint>

#define CHUNK 1024          // floats per early-exit quantum (4 KB)
#define NSUB  8             // sub-blocks of 128 floats (one float4 per lane)

__device__ int g_row_counter;

__global__ void reset_counter_kernel() { g_row_counter = 0; }

// ---------------------------------------------------------------------------
// Warp-autonomous bidirectional inverse-CDF sampler.
//   sample = #{v : r > csum[v]},  csum monotone (p >= 0), sum(p) ~= 1.
// r <= 0.5: scan forward, stop at first chunk where cumsum >= r, count
//           ordered prefixes < r inside the (in-register) chunk.
// r >  0.5: scan backward with q = 1-r; sample = #{k in [1..V] : suf[k] > q}
//           (suffix monotone decreasing). Stop at first chunk whose suffix
//           total exceeds q; count in-register.
// One warp per row, rows distributed via global atomic counter. No barriers.
// Output dtype float32 (samples <= 32000 exact in fp32).
// ---------------------------------------------------------------------------
__global__ void __launch_bounds__(256) sampler_kernel(
    const float* __restrict__ p, const float* __restrict__ rng,
    float* __restrict__ out, int V, int rows)
{
    const int lane = threadIdx.x & 31;
    const int nch  = (V + CHUNK - 1) / CHUNK;

    for (;;) {
        int row;
        if (lane == 0) row = atomicAdd(&g_row_counter, 1);
        row = __shfl_sync(0xFFFFFFFFu, row, 0);
        if (row >= rows) return;

        const float r = __ldg(&rng[row]);
        const float* __restrict__ prow = p + (size_t)row * V;

        if (r <= 0.5f) {
            // ---------------- forward scan ----------------
            float acc = 0.0f;
            float res = (float)V;                  // fallback (cannot trigger: sum ~1 > r)
            for (int c = 0; c < nch; c++) {
                const int lo = c * CHUNK;
                const int hi = min(V, lo + CHUNK);
                float4 x[NSUB]; float s4[NSUB];
                #pragma unroll
                for (int j = 0; j < NSUB; j++) {
                    const int idx = lo + j * 128 + lane * 4;
                    float4 a = make_float4(0.f, 0.f, 0.f, 0.f);
                    if (idx + 4 <= hi) {
                        a = *reinterpret_cast<const float4*>(prow + idx);
                    } else {
                        if (idx + 0 < hi) a.x = prow[idx + 0];
                        if (idx + 1 < hi) a.y = prow[idx + 1];
                        if (idx + 2 < hi) a.z = prow[idx + 2];
                    }
                    x[j]  = a;
                    s4[j] = (a.x + a.y) + (a.z + a.w);
                }
                float tot = ((s4[0] + s4[1]) + (s4[2] + s4[3]))
                          + ((s4[4] + s4[5]) + (s4[6] + s4[7]));
                #pragma unroll
                for (int d = 16; d > 0; d >>= 1)
                    tot += __shfl_xor_sync(0xFFFFFFFFu, tot, d);

                if (acc + tot >= r) {
                    // crossing inside this chunk: ordered in-register recount
                    float carry = acc;
                    int cnt = 0;
                    #pragma unroll
                    for (int j = 0; j < NSUB; j++) {
                        float scan = s4[j];
                        #pragma unroll
                        for (int d = 1; d < 32; d <<= 1) {
                            float y = __shfl_up_sync(0xFFFFFFFFu, scan, d);
                            if (lane >= d) scan += y;
                        }
                        const int idx = lo + j * 128 + lane * 4;
                        const float c0 = carry + (scan - s4[j]) + x[j].x;
                        const float c1 = c0 + x[j].y;
                        const float c2 = c1 + x[j].z;
                        const float c3 = c2 + x[j].w;
                        cnt += (idx + 0 < hi && c0 < r);
                        cnt += (idx + 1 < hi && c1 < r);
                        cnt += (idx + 2 < hi && c2 < r);
                        cnt += (idx + 3 < hi && c3 < r);
                        carry += __shfl_sync(0xFFFFFFFFu, scan, 31);
                    }
                    #pragma unroll
                    for (int d = 16; d > 0; d >>= 1)
                        cnt += __shfl_xor_sync(0xFFFFFFFFu, cnt, d);
                    res = (float)(lo + cnt);       // all v < lo have csum <= acc < r
                    break;
                }
                acc += tot;
            }
            if (lane == 0) out[row] = res;
        } else {
            // ---------------- backward scan ----------------
            const float q = 1.0f - r;              // count k with suf[k] > q
            float acc = 0.0f;                      // suffix sum of scanned chunks
            float res = 0.0f;                      // fallback (cannot trigger: sum ~1 > q)
            for (int c = 0; c < nch; c++) {
                const int hi = V - c * CHUNK;
                const int lo = max(0, hi - CHUNK);
                float4 x[NSUB]; float s4[NSUB];
                #pragma unroll
                for (int j = 0; j < NSUB; j++) {
                    const int idx = lo + j * 128 + lane * 4;
                    float4 a = make_float4(0.f, 0.f, 0.f, 0.f);
                    if (idx + 4 <= hi) {
                        a = *reinterpret_cast<const float4*>(prow + idx);
                    } else {
                        if (idx + 0 < hi) a.x = prow[idx + 0];
                        if (idx + 1 < hi) a.y = prow[idx + 1];
                        if (idx + 2 < hi) a.z = prow[idx + 2];
                    }
                    x[j]  = a;
                    s4[j] = (a.x + a.y) + (a.z + a.w);
                }
                float tot = ((s4[0] + s4[1]) + (s4[2] + s4[3]))
                          + ((s4[4] + s4[5]) + (s4[6] + s4[7]));
                #pragma unroll
                for (int d = 16; d > 0; d >>= 1)
                    tot += __shfl_xor_sync(0xFFFFFFFFu, tot, d);

                if (acc + tot > q) {
                    // crossing inside this chunk: reverse ordered recount.
                    // count over elements v in [lo, hi) of (suf[v] > q);
                    // sample = lo + cnt - 1 + (acc > q)   [k-range bookkeeping]
                    float carry = acc;             // suffix of elements >= hi
                    int cnt = 0;
                    #pragma unroll
                    for (int j = NSUB - 1; j >= 0; j--) {
                        float rs = s4[j];          // reverse inclusive scan
                        #pragma unroll
                        for (int d = 1; d < 32; d <<= 1) {
                            float y = __shfl_down_sync(0xFFFFFFFFu, rs, d);
                            if (lane < 32 - d) rs += y;
                        }
                        const float rev_excl = rs - s4[j];   // lanes above this one
                        const int idx = lo + j * 128 + lane * 4;
                        const float sw = carry + rev_excl + x[j].w;  // suf[idx+3]
                        const float sz = sw + x[j].z;                // suf[idx+2]
                        const float sy = sz + x[j].y;                // suf[idx+1]
                        const float sx = sy + x[j].x;                // suf[idx]
                        cnt += (idx + 3 < hi && sw > q);
                        cnt += (idx + 2 < hi && sz > q);
                        cnt += (idx + 1 < hi && sy > q);
                        cnt += (idx + 0 < hi && sx > q);
                        carry += __shfl_sync(0xFFFFFFFFu, rs, 0);
                    }
                    #pragma unroll
                    for (int d = 16; d > 0; d >>= 1)
                        cnt += __shfl_xor_sync(0xFFFFFFFFu, cnt, d);
                    res = (float)(lo + cnt - 1 + (acc > q ? 1 : 0));
                    break;
                }
                acc += tot;
            }
            if (lane == 0) out[row] = res;
        }
    }
}

extern "C" void kernel_launch(void* const* d_in, const int* in_sizes, int n_in,
                              void* d_out, int out_size) {
    // Resolve inputs by element count (p is the huge one, rng has `rows`).
    int ip = 0;
    for (int i = 1; i < n_in; i++)
        if (in_sizes[i] > in_sizes[ip]) ip = i;
    const float* p = (const float*)d_in[ip];

    const int rows = out_size;                       // B*T = 8192
    int ir = (ip == 0) ? 1 : 0;
    for (int i = 0; i < n_in; i++)
        if (i != ip && in_sizes[i] == rows) { ir = i; break; }
    const float* rng = (const float*)d_in[ir];

    float* out = (float*)d_out;                      // output dtype: float32

    const long long pelems = (long long)in_sizes[ip];
    const int V = (int)(pelems / rows);              // 32000

    reset_counter_kernel<<<1, 1>>>();
    sampler_kernel<<<1184, 256>>>(p, rng, out, V, rows);
}